// round 11
// baseline (speedup 1.0000x reference)
#include <cuda_runtime.h>
#include <cstdint>

#define NMAX 100000
#define EMAX 1600000
#define D 64

// ---- scratch (device globals; no runtime allocation) ----
__device__ float g_q[NMAX * D];
__device__ float g_kf[NMAX * 2 * D];   // interleaved: [node][(col/2)*4 + {k0,k1,f0,f1}]
__device__ int   g_deg[NMAX];
__device__ int   g_off[NMAX];
__device__ int   g_cur[NMAX];
__device__ int   g_srcs[EMAX];
__device__ int   g_tmp[NMAX];
__device__ int   g_bsum[256];

// ---------------------------------------------------------------------------
// count: per-dst degree histogram (g_deg zeroed by memset node)
// ---------------------------------------------------------------------------
__global__ void count_kernel(const int* __restrict__ dst, int e) {
    int i = blockIdx.x * blockDim.x + threadIdx.x;
    if (i < e) atomicAdd(&g_deg[__ldg(&dst[i])], 1);
}

// ---------------------------------------------------------------------------
// scan pass 1: per-block (1024) exclusive scan -> g_tmp, block sums -> g_bsum
// ---------------------------------------------------------------------------
__global__ __launch_bounds__(1024) void scan1_kernel(int n) {
    __shared__ int sh[1024];
    int t = threadIdx.x;
    int i = blockIdx.x * 1024 + t;
    int v = (i < n) ? g_deg[i] : 0;
    sh[t] = v;
    __syncthreads();
    #pragma unroll
    for (int off = 1; off < 1024; off <<= 1) {
        int x = (t >= off) ? sh[t - off] : 0;
        __syncthreads();
        sh[t] += x;
        __syncthreads();
    }
    if (i < n) g_tmp[i] = sh[t] - v;
    if (t == 1023) g_bsum[blockIdx.x] = sh[1023];
}

// ---------------------------------------------------------------------------
// scan pass 2+3 fused: each block re-scans (<=128) block sums in smem,
// applies its block offset -> g_off / g_cur.
// ---------------------------------------------------------------------------
__global__ __launch_bounds__(1024) void scan23_kernel(int n, int nb) {
    __shared__ int sh[128];
    int t = threadIdx.x;
    if (t < 128) sh[t] = (t < nb) ? g_bsum[t] : 0;
    __syncthreads();
    #pragma unroll
    for (int off = 1; off < 128; off <<= 1) {
        int x = (t >= off && t < 128) ? sh[t - off] : 0;
        __syncthreads();
        if (t < 128) sh[t] += x;   // inclusive scan
        __syncthreads();
    }
    int base = (blockIdx.x == 0) ? 0 : sh[blockIdx.x - 1];
    int i = blockIdx.x * 1024 + t;
    if (i < n) {
        int o = g_tmp[i] + base;
        g_off[i] = o;
        g_cur[i] = o;
    }
}

// ---------------------------------------------------------------------------
// scatter: standalone, lean (no smem), high occupancy
// ---------------------------------------------------------------------------
__global__ void scatter_kernel(const int* __restrict__ src,
                               const int* __restrict__ dst, int e) {
    int i = blockIdx.x * blockDim.x + threadIdx.x;
    if (i < e) {
        int p = atomicAdd(&g_cur[__ldg(&dst[i])], 1);
        g_srcs[p] = __ldg(&src[i]);
    }
}

// ---------------------------------------------------------------------------
// Projection v3: 128 threads/block, 64-node x 64-col tile.
// Thread micro-tile: 4 rows x 8 cols, accumulators packed along COLUMN pairs
// so B pairs load directly as u64 from shared (no B splat).
// Per k-step: 1 LDS.128 (A rows) + 2 LDS.128 (B cols) + 4 A-splats + 16 FFMA2.
// ---------------------------------------------------------------------------
__global__ __launch_bounds__(128) void proj_kernel(
    const float* __restrict__ feat,
    const float* __restrict__ Wq, const float* __restrict__ bq,
    const float* __restrict__ Wk, const float* __restrict__ bk,
    const float* __restrict__ Wf, const float* __restrict__ bf,
    int n)
{
    __shared__ float fs[64][68];  // fs[k][node_local], padded, rows 16B-aligned
    __shared__ float ws[64][64];  // ws[k][col]

    int node0 = blockIdx.x * 64;
    int t = threadIdx.x;

    // load feat tile transposed: fs[k][m] = feat[node0+m][k]  (once)
    {
        int kcol = t & 63, half = t >> 6;
        #pragma unroll 8
        for (int m = half; m < 64; m += 2) {
            int row = node0 + m;
            if (row >= n) row = n - 1;  // clamp (stores are guarded)
            fs[kcol][m] = feat[row * 64 + kcol];
        }
    }

    int r = t >> 3;   // 0..15 -> rows 4r..4r+3
    int c = t & 7;    // 0..7  -> cols 8c..8c+7

    #pragma unroll
    for (int which = 0; which < 3; which++) {
        const float* W    = (which == 0) ? Wq : (which == 1) ? Wk : Wf;
        const float* bias = (which == 0) ? bq : (which == 1) ? bk : bf;

        __syncthreads();   // fs ready (pass 0) / prior pass done reading ws
        #pragma unroll
        for (int i = 0; i < 8; i++)
            ((float4*)ws)[t + i * 128] = ((const float4*)W)[t + i * 128];
        __syncthreads();

        // acc[p][j]: row 4r+p, packed cols (8c+2j, 8c+2j+1)
        unsigned long long acc[4][4];
        #pragma unroll
        for (int p = 0; p < 4; p++)
            #pragma unroll
            for (int j = 0; j < 4; j++) acc[p][j] = 0ull;

        #pragma unroll 4
        for (int kk = 0; kk < 64; kk++) {
            float4 av = *(const float4*)&fs[kk][4 * r];          // A rows
            ulonglong2 bA = *(const ulonglong2*)&ws[kk][c * 8];  // B col pairs 0,1
            ulonglong2 bB = *(const ulonglong2*)&ws[kk][c * 8 + 4]; // pairs 2,3
            unsigned long long b2[4] = {bA.x, bA.y, bB.x, bB.y};
            float a[4] = {av.x, av.y, av.z, av.w};
            #pragma unroll
            for (int p = 0; p < 4; p++) {
                unsigned long long a2;
                asm("mov.b64 %0, {%1, %1};" : "=l"(a2)
                    : "r"(__float_as_uint(a[p])));
                #pragma unroll
                for (int j = 0; j < 4; j++)
                    asm("fma.rn.f32x2 %0, %1, %2, %0;"
                        : "+l"(acc[p][j]) : "l"(a2), "l"(b2[j]));
            }
        }

        // packed bias pairs
        ulonglong2 biA = *(const ulonglong2*)&bias[c * 8];
        ulonglong2 biB = *(const ulonglong2*)&bias[c * 8 + 4];
        unsigned long long bias2[4] = {biA.x, biA.y, biB.x, biB.y};

        #pragma unroll
        for (int p = 0; p < 4; p++) {
            unsigned long long o[4];
            #pragma unroll
            for (int j = 0; j < 4; j++)
                asm("add.rn.f32x2 %0, %1, %2;"
                    : "=l"(o[j]) : "l"(acc[p][j]), "l"(bias2[j]));

            int node = node0 + 4 * r + p;
            if (node < n) {
                if (which == 0) {
                    ulonglong2 v0; v0.x = o[0]; v0.y = o[1];
                    ulonglong2 v1; v1.x = o[2]; v1.y = o[3];
                    *(ulonglong2*)&g_q[(size_t)node * 64 + c * 8]     = v0;
                    *(ulonglong2*)&g_q[(size_t)node * 64 + c * 8 + 4] = v1;
                } else {
                    // col pair (8c+2j, 8c+2j+1) -> kf[node*128 + (4c+j)*4 + add]
                    int add = (which == 1) ? 0 : 2;
                    #pragma unroll
                    for (int j = 0; j < 4; j++)
                        *(unsigned long long*)
                            &g_kf[(size_t)node * 128 + (4 * c + j) * 4 + add] = o[j];
                }
            }
        }
    }
}

// ---------------------------------------------------------------------------
// Aggregation: one warp per destination node; edge pairs for ILP; one
// LDG.128 per lane fetches k-pair AND f-pair (interleaved kf).
// ---------------------------------------------------------------------------
__global__ __launch_bounds__(256) void agg_kernel(float* __restrict__ out, int n) {
    int w = (int)((blockIdx.x * 256u + threadIdx.x) >> 5);
    int lane = threadIdx.x & 31;
    if (w >= n) return;

    int beg = g_off[w];
    int deg = g_deg[w];

    float2 qv = *(const float2*)&g_q[(size_t)w * 64 + lane * 2];
    float qx = qv.x, qy = qv.y;

    float m = -1e30f;
    float s = 0.f;
    float ax = 0.f, ay = 0.f;

    for (int base = 0; base < deg; base += 32) {
        int cnt = min(32, deg - base);
        int myidx = (lane < cnt) ? __ldg(&g_srcs[beg + base + lane]) : 0;

        int j = 0;
        for (; j + 1 < cnt; j += 2) {
            int s0 = __shfl_sync(0xffffffffu, myidx, j);
            int s1 = __shfl_sync(0xffffffffu, myidx, j + 1);
            float4 a = __ldg((const float4*)&g_kf[(size_t)s0 * 128 + lane * 4]);
            float4 b = __ldg((const float4*)&g_kf[(size_t)s1 * 128 + lane * 4]);

            float d0 = a.x * qx + a.y * qy;
            float d1 = b.x * qx + b.y * qy;
            #pragma unroll
            for (int o = 16; o; o >>= 1) {
                d0 += __shfl_xor_sync(0xffffffffu, d0, o);
                d1 += __shfl_xor_sync(0xffffffffu, d1, o);
            }

            float e0 = d0 > 0.f ? d0 : 0.2f * d0;
            float e1 = d1 > 0.f ? d1 : 0.2f * d1;

            float mb = fmaxf(e0, e1);
            float mn = fmaxf(m, mb);
            float sc = __expf(m - mn);
            float w0 = __expf(e0 - mn);
            float w1 = __expf(e1 - mn);
            s  = s  * sc + w0 + w1;
            ax = ax * sc + w0 * a.z + w1 * b.z;
            ay = ay * sc + w0 * a.w + w1 * b.w;
            m = mn;
        }
        if (j < cnt) {
            int s0 = __shfl_sync(0xffffffffu, myidx, j);
            float4 a = __ldg((const float4*)&g_kf[(size_t)s0 * 128 + lane * 4]);
            float d0 = a.x * qx + a.y * qy;
            #pragma unroll
            for (int o = 16; o; o >>= 1) d0 += __shfl_xor_sync(0xffffffffu, d0, o);
            float e0 = d0 > 0.f ? d0 : 0.2f * d0;
            float mn = fmaxf(m, e0);
            float sc = __expf(m - mn);
            float w0 = __expf(e0 - mn);
            s  = s  * sc + w0;
            ax = ax * sc + w0 * a.z;
            ay = ay * sc + w0 * a.w;
            m = mn;
        }
    }

    float inv = (deg > 0) ? 1.f / s : 0.f;
    float2 o2;
    o2.x = ax * inv;
    o2.y = ay * inv;
    *(float2*)&out[(size_t)w * 64 + lane * 2] = o2;
}

// ---------------------------------------------------------------------------
// Launch: fork the CSR build onto a side stream so it co-runs with proj.
// ---------------------------------------------------------------------------
extern "C" void kernel_launch(void* const* d_in, const int* in_sizes, int n_in,
                              void* d_out, int out_size) {
    const float* feat = (const float*)d_in[0];
    const int*   src  = (const int*)d_in[1];
    const int*   dst  = (const int*)d_in[2];
    const float* Wq   = (const float*)d_in[3];
    const float* bq   = (const float*)d_in[4];
    const float* Wk   = (const float*)d_in[5];
    const float* bk   = (const float*)d_in[6];
    const float* Wf   = (const float*)d_in[7];
    const float* bf   = (const float*)d_in[8];
    float* out = (float*)d_out;

    int n = in_sizes[0] / D;   // nodes
    int e = in_sizes[1];       // edges
    int nb = (n + 1023) / 1024;

    void* degp = nullptr;
    cudaGetSymbolAddress(&degp, g_deg);

    // side stream + fork/join events (created per call; never destroyed here
    // because capture may still be active when we return — bounded leak over
    // the harness's few kernel_launch invocations)
    cudaStream_t s2;
    cudaStreamCreateWithFlags(&s2, cudaStreamNonBlocking);
    cudaEvent_t evFork, evJoin;
    cudaEventCreateWithFlags(&evFork, cudaEventDisableTiming);
    cudaEventCreateWithFlags(&evJoin, cudaEventDisableTiming);

    // ---- fork
    cudaEventRecord(evFork, 0);
    cudaStreamWaitEvent(s2, evFork, 0);

    // branch A (main stream): projections
    proj_kernel<<<(n + 63) / 64, 128>>>(feat, Wq, bq, Wk, bk, Wf, bf, n);

    // branch B (side stream): CSR build by dst
    cudaMemsetAsync(degp, 0, (size_t)n * sizeof(int), s2);
    count_kernel<<<(e + 255) / 256, 256, 0, s2>>>(dst, e);
    scan1_kernel<<<nb, 1024, 0, s2>>>(n);
    scan23_kernel<<<nb, 1024, 0, s2>>>(n, nb);
    scatter_kernel<<<(e + 255) / 256, 256, 0, s2>>>(src, dst, e);

    // ---- join
    cudaEventRecord(evJoin, s2);
    cudaStreamWaitEvent(0, evJoin, 0);

    // aggregation (needs both branches)
    agg_kernel<<<(n + 7) / 8, 256>>>(out, n);
}